// round 4
// baseline (speedup 1.0000x reference)
#include <cuda_runtime.h>
#include <cuda_bf16.h>
#include <math_constants.h>

// Problem constants
#define T_TOKENS 4096
#define HIDDEN   2048
#define N_EXP    8
#define H4       (HIDDEN / 4)          // 512 float4 per hidden row

// Output layout (floats), outputs concatenated:
//   [0, 32768)                router_scores [E, T]
//   [32768, +67108864)        router_indices [E*T, H] (value = t, as float)
//   [67141632, 67174400)      router_probs [E*T, 1] == scores flattened
#define SCORES_OFF 0
#define IDX_OFF    (N_EXP * T_TOKENS)                       // 32768
#define IDX_ELEMS  ((size_t)N_EXP * T_TOKENS * HIDDEN)      // 67108864
#define PROBS_OFF  (IDX_OFF + IDX_ELEMS)                    // 67141632

// One homogeneous block type:
//   320 threads = 10 warps.
//   warps 0..7  : fill  (2048 float4 per warp -> 16384 f4/block)
//   warps 8..9  : logits for 4 tokens (each warp does half of hidden dim)
#define NBLOCKS     1024
#define NTHREADS    320
#define FILL_WARPS  8
#define F4_PER_BLOCK 16384            // 1024 * 16384 = 16,777,216 total
#define TPB 4                         // tokens per block

__global__ __launch_bounds__(NTHREADS, 3)
void router_fused_kernel(const float* __restrict__ hs,
                         const float* __restrict__ wr,
                         float* __restrict__ out) {
    __shared__ float part[2][TPB][N_EXP];   // 256 B

    const int warp = threadIdx.x >> 5;
    const int lane = threadIdx.x & 31;
    const unsigned b = blockIdx.x;

    if (warp < FILL_WARPS) {
        // ------------------------- fill warps -------------------------
        float4* __restrict__ out4 = (float4*)(out + IDX_OFF);
        const size_t base = (size_t)b * F4_PER_BLOCK + warp * 2048 + lane;
#pragma unroll 8
        for (int j = 0; j < 64; j++) {
            const size_t i = base + (size_t)j * 32;
            const float v = (float)((i >> 9) & (T_TOKENS - 1));
            __stcs(&out4[i], make_float4(v, v, v, v));
        }
        return;
    }

    // ------------------------- logits warps -------------------------
    const int lw = warp - FILL_WARPS;          // 0 or 1: which hidden half
    const int t0 = (int)b * TPB;               // tokens t0..t0+3

    const float4* __restrict__ hs4 = (const float4*)hs;
    const float4* __restrict__ w4  = (const float4*)wr;

    float acc[TPB][N_EXP];
#pragma unroll
    for (int a = 0; a < TPB; a++)
#pragma unroll
        for (int e = 0; e < N_EXP; e++) acc[a][e] = 0.f;

#pragma unroll
    for (int ii = 0; ii < 8; ii++) {           // 8 iters * 32 lanes = 256 f4 = H4/2
        const int i = lw * 256 + ii * 32 + lane;
        float4 x[TPB];
#pragma unroll
        for (int a = 0; a < TPB; a++)
            x[a] = hs4[(size_t)(t0 + a) * H4 + i];
#pragma unroll
        for (int e = 0; e < N_EXP; e++) {
            const float4 wv = __ldg(&w4[e * H4 + i]);
#pragma unroll
            for (int a = 0; a < TPB; a++) {
                acc[a][e] += x[a].x * wv.x + x[a].y * wv.y
                           + x[a].z * wv.z + x[a].w * wv.w;
            }
        }
    }

    // warp reduction (lane 0 keeps the sums)
#pragma unroll
    for (int a = 0; a < TPB; a++)
#pragma unroll
        for (int e = 0; e < N_EXP; e++)
#pragma unroll
            for (int o = 16; o > 0; o >>= 1)
                acc[a][e] += __shfl_down_sync(0xffffffffu, acc[a][e], o);

    if (lane == 0) {
#pragma unroll
        for (int a = 0; a < TPB; a++)
#pragma unroll
            for (int e = 0; e < N_EXP; e++)
                part[lw][a][e] = acc[a][e];
    }

    // sync the two logits warps only (named barrier, 64 threads)
    asm volatile("bar.sync 1, 64;" ::: "memory");

    if (lw == 0 && lane < TPB) {
        const int a = lane;
        const int t = t0 + a;
        float lg[N_EXP];
#pragma unroll
        for (int e = 0; e < N_EXP; e++)
            lg[e] = part[0][a][e] + part[1][a][e];

        // top-1
        float b1 = -CUDART_INF_F; int i1 = 0;
#pragma unroll
        for (int e = 0; e < N_EXP; e++)
            if (lg[e] > b1) { b1 = lg[e]; i1 = e; }
        // top-2 (excluding i1)
        float b2 = -CUDART_INF_F; int i2 = -1;
#pragma unroll
        for (int e = 0; e < N_EXP; e++)
            if (e != i1 && lg[e] > b2) { b2 = lg[e]; i2 = e; }

        const float s1 = 1.f / (1.f + __expf(-b1));
        const float s2 = 1.f / (1.f + __expf(-b2));
#pragma unroll
        for (int e = 0; e < N_EXP; e++) {
            const float s = (e == i1) ? s1 : ((e == i2) ? s2 : 0.f);
            out[SCORES_OFF + (size_t)e * T_TOKENS + t] = s;
            out[PROBS_OFF  + (size_t)e * T_TOKENS + t] = s;
        }
    }
}

extern "C" void kernel_launch(void* const* d_in, const int* in_sizes, int n_in,
                              void* d_out, int out_size) {
    const float* hs = (const float*)d_in[0];  // [T, H] fp32
    const float* wr = (const float*)d_in[1];  // [E, H] fp32
    float* out = (float*)d_out;

    router_fused_kernel<<<NBLOCKS, NTHREADS>>>(hs, wr, out);
}

// round 5
// speedup vs baseline: 1.3358x; 1.3358x over previous
#include <cuda_runtime.h>
#include <cuda_bf16.h>
#include <math_constants.h>

// Problem constants
#define T_TOKENS 4096
#define HIDDEN   2048
#define N_EXP    8
#define H4       (HIDDEN / 4)          // 512 float4 per hidden row

// Output layout (floats), outputs concatenated:
//   [0, 32768)                router_scores [E, T]
//   [32768, +67108864)        router_indices [E*T, H] (value = t, as float)
//   [67141632, 67174400)      router_probs [E*T, 1] == scores flattened
#define SCORES_OFF 0
#define IDX_OFF    (N_EXP * T_TOKENS)                       // 32768
#define IDX_ELEMS  ((size_t)N_EXP * T_TOKENS * HIDDEN)      // 67108864
#define PROBS_OFF  (IDX_OFF + IDX_ELEMS)                    // 67141632

// ---------------------------------------------------------------------------
// Kernel 1: logits + top-2 + sigmoid scatter.
// 256 blocks x 256 threads, 2 tokens per warp -> 2048 warps, 4096 tokens.
// w_router is 64 KB: L1-resident per SM after first touch.
// ---------------------------------------------------------------------------
#define TPW 2

__global__ __launch_bounds__(256, 8)
void router_logits_kernel(const float* __restrict__ hs,
                          const float* __restrict__ wr,
                          float* __restrict__ out) {
    const int warp = threadIdx.x >> 5;
    const int lane = threadIdx.x & 31;
    const int t0 = (blockIdx.x * 8 + warp) * TPW;

    const float4* __restrict__ hs4 = (const float4*)hs;
    const float4* __restrict__ w4  = (const float4*)wr;

    float acc[TPW][N_EXP];
#pragma unroll
    for (int a = 0; a < TPW; a++)
#pragma unroll
        for (int e = 0; e < N_EXP; e++) acc[a][e] = 0.f;

#pragma unroll
    for (int ii = 0; ii < H4 / 32; ii++) {       // 16 iterations, fully unrolled
        const int i = ii * 32 + lane;
        float4 x[TPW];
#pragma unroll
        for (int a = 0; a < TPW; a++)
            x[a] = hs4[(size_t)(t0 + a) * H4 + i];
#pragma unroll
        for (int e = 0; e < N_EXP; e++) {
            const float4 wv = __ldg(&w4[e * H4 + i]);
#pragma unroll
            for (int a = 0; a < TPW; a++) {
                acc[a][e] += x[a].x * wv.x + x[a].y * wv.y
                           + x[a].z * wv.z + x[a].w * wv.w;
            }
        }
    }

    // butterfly warp reduction
#pragma unroll
    for (int a = 0; a < TPW; a++)
#pragma unroll
        for (int e = 0; e < N_EXP; e++)
#pragma unroll
            for (int o = 16; o > 0; o >>= 1)
                acc[a][e] += __shfl_xor_sync(0xffffffffu, acc[a][e], o);

    if (lane == 0) {
#pragma unroll
        for (int a = 0; a < TPW; a++) {
            const int t = t0 + a;
            float b1 = -CUDART_INF_F; int i1 = 0;
#pragma unroll
            for (int e = 0; e < N_EXP; e++)
                if (acc[a][e] > b1) { b1 = acc[a][e]; i1 = e; }
            float b2 = -CUDART_INF_F; int i2 = -1;
#pragma unroll
            for (int e = 0; e < N_EXP; e++)
                if (e != i1 && acc[a][e] > b2) { b2 = acc[a][e]; i2 = e; }

            const float s1 = 1.f / (1.f + __expf(-b1));
            const float s2 = 1.f / (1.f + __expf(-b2));
#pragma unroll
            for (int e = 0; e < N_EXP; e++) {
                const float s = (e == i1) ? s1 : ((e == i2) ? s2 : 0.f);
                out[SCORES_OFF + (size_t)e * T_TOKENS + t] = s;
                out[PROBS_OFF  + (size_t)e * T_TOKENS + t] = s;
            }
        }
    }
}

// ---------------------------------------------------------------------------
// Kernel 2: fill router_indices region (268 MB pattern write).
// Exact R1 configuration: 65536 blocks x 256 threads, 1 float4/thread.
// Measured standalone: 37.9 us @ ~7 TB/s effective.
// ---------------------------------------------------------------------------
__global__ __launch_bounds__(256)
void fill_indices_kernel(float4* __restrict__ out4) {
    const size_t i = (size_t)blockIdx.x * blockDim.x + threadIdx.x;
    const float v = (float)((i >> 9) & (T_TOKENS - 1));
    __stcs(&out4[i], make_float4(v, v, v, v));
}

extern "C" void kernel_launch(void* const* d_in, const int* in_sizes, int n_in,
                              void* d_out, int out_size) {
    const float* hs = (const float*)d_in[0];  // [T, H] fp32
    const float* wr = (const float*)d_in[1];  // [E, H] fp32
    float* out = (float*)d_out;

    router_logits_kernel<<<256, 256>>>(hs, wr, out);

    const size_t n4 = IDX_ELEMS / 4;          // 16,777,216
    fill_indices_kernel<<<(unsigned)(n4 / 256), 256>>>((float4*)(out + IDX_OFF));
}

// round 6
// speedup vs baseline: 1.7914x; 1.3411x over previous
#include <cuda_runtime.h>
#include <cuda_bf16.h>
#include <math_constants.h>

// Problem constants
#define T_TOKENS 4096
#define HIDDEN   2048
#define N_EXP    8
#define H4       (HIDDEN / 4)          // 512 float4 per hidden row

// Output layout (floats), outputs concatenated:
//   [0, 32768)                router_scores [E, T]
//   [32768, +67108864)        router_indices [E*T, H] (value = t, as float)
//   [67141632, 67174400)      router_probs [E*T, 1] == scores flattened
#define SCORES_OFF 0
#define IDX_OFF    (N_EXP * T_TOKENS)                       // 32768
#define IDX_ELEMS  ((size_t)N_EXP * T_TOKENS * HIDDEN)      // 67108864
#define PROBS_OFF  (IDX_OFF + IDX_ELEMS)                    // 67141632

// ---------------------------------------------------------------------------
// Kernel 1: logits + top-2 + sigmoid scatter.
// 256 blocks x 256 threads, 2 tokens/warp. launch_bounds(256,2) -> 128-reg
// budget: NO SPILLS (R5 used (256,8) = 32 regs and spilled to local).
// ---------------------------------------------------------------------------
#define TPW 2

__global__ __launch_bounds__(256, 2)
void router_logits_kernel(const float* __restrict__ hs,
                          const float* __restrict__ wr,
                          float* __restrict__ out) {
    const int warp = threadIdx.x >> 5;
    const int lane = threadIdx.x & 31;
    const int t0 = (blockIdx.x * 8 + warp) * TPW;

    const float4* __restrict__ hs4 = (const float4*)hs;
    const float4* __restrict__ w4  = (const float4*)wr;

    float acc[TPW][N_EXP];
#pragma unroll
    for (int a = 0; a < TPW; a++)
#pragma unroll
        for (int e = 0; e < N_EXP; e++) acc[a][e] = 0.f;

#pragma unroll 4
    for (int ii = 0; ii < H4 / 32; ii++) {       // 16 iterations
        const int i = ii * 32 + lane;
        float4 x[TPW];
#pragma unroll
        for (int a = 0; a < TPW; a++)
            x[a] = hs4[(size_t)(t0 + a) * H4 + i];
#pragma unroll
        for (int e = 0; e < N_EXP; e++) {
            const float4 wv = __ldg(&w4[e * H4 + i]);
#pragma unroll
            for (int a = 0; a < TPW; a++) {
                acc[a][e] += x[a].x * wv.x + x[a].y * wv.y
                           + x[a].z * wv.z + x[a].w * wv.w;
            }
        }
    }

    // butterfly warp reduction
#pragma unroll
    for (int a = 0; a < TPW; a++)
#pragma unroll
        for (int e = 0; e < N_EXP; e++)
#pragma unroll
            for (int o = 16; o > 0; o >>= 1)
                acc[a][e] += __shfl_xor_sync(0xffffffffu, acc[a][e], o);

    if (lane == 0) {
#pragma unroll
        for (int a = 0; a < TPW; a++) {
            const int t = t0 + a;
            float b1 = -CUDART_INF_F; int i1 = 0;
#pragma unroll
            for (int e = 0; e < N_EXP; e++)
                if (acc[a][e] > b1) { b1 = acc[a][e]; i1 = e; }
            float b2 = -CUDART_INF_F; int i2 = -1;
#pragma unroll
            for (int e = 0; e < N_EXP; e++)
                if (e != i1 && acc[a][e] > b2) { b2 = acc[a][e]; i2 = e; }

            const float s1 = 1.f / (1.f + __expf(-b1));
            const float s2 = 1.f / (1.f + __expf(-b2));
#pragma unroll
            for (int e = 0; e < N_EXP; e++) {
                const float s = (e == i1) ? s1 : ((e == i2) ? s2 : 0.f);
                out[SCORES_OFF + (size_t)e * T_TOKENS + t] = s;
                out[PROBS_OFF  + (size_t)e * T_TOKENS + t] = s;
            }
        }
    }
}

// ---------------------------------------------------------------------------
// Kernel 2: fill router_indices region (268 MB pattern write).
// Fatter blocks: 8192 blocks x 256 threads x 8 float4/thread (32 KB/block)
// to amortize CTA turnover (R5: 65536 tiny blocks -> occ 24%, CTA-rate bound).
// ---------------------------------------------------------------------------
#define FILL_F4_PER_THREAD 8
#define FILL_BLOCKS (16777216 / (256 * FILL_F4_PER_THREAD))   // 8192

__global__ __launch_bounds__(256)
void fill_indices_kernel(float4* __restrict__ out4) {
    const size_t base = (size_t)blockIdx.x * (256 * FILL_F4_PER_THREAD) + threadIdx.x;
#pragma unroll
    for (int j = 0; j < FILL_F4_PER_THREAD; j++) {
        const size_t i = base + (size_t)j * 256;
        const float v = (float)((i >> 9) & (T_TOKENS - 1));
        __stcs(&out4[i], make_float4(v, v, v, v));
    }
}

extern "C" void kernel_launch(void* const* d_in, const int* in_sizes, int n_in,
                              void* d_out, int out_size) {
    const float* hs = (const float*)d_in[0];  // [T, H] fp32
    const float* wr = (const float*)d_in[1];  // [E, H] fp32
    float* out = (float*)d_out;

    router_logits_kernel<<<256, 256>>>(hs, wr, out);
    fill_indices_kernel<<<FILL_BLOCKS, 256>>>((float4*)(out + IDX_OFF));
}